// round 14
// baseline (speedup 1.0000x reference)
#include <cuda_runtime.h>
#include <cuda_pipeline.h>

#define H2    1024
#define SEQN  65536
#define NOC   64               // o-chunks (16 rows each) for k1a
#define K2B   (SEQN / 32)      // 2048 k2 blocks, 32 rows each

// Scratch (allocation-free rule: device globals)
__device__ __align__(16) float g_vpart[NOC][H2];
__device__ __align__(16) float g_v[H2];
__device__ __align__(16) float g_m[K2B];   // per-block energy max
__device__ __align__(16) float g_s[K2B];   // per-block sum of exp(e - m_b)

// K1a: partial v over one 16-row o-chunk, in-block fold 4->1.
// grid (4 h-quarters, NOC) = 256 blocks x 256 thr (proven shape).
__global__ void __launch_bounds__(256) k1a_v(const float* __restrict__ W,
                                             const float* __restrict__ wv) {
    __shared__ __align__(16) float4 red[256];
    const int osub = threadIdx.x >> 6;          // 0..3
    const int hl   = threadIdx.x & 63;          // local float4 index
    const int h4   = blockIdx.x * 64 + hl;      // global float4 index over h
    const int o0   = blockIdx.y * 16;

    float4 acc = make_float4(0.f, 0.f, 0.f, 0.f);
#pragma unroll
    for (int i = 0; i < 4; i++) {               // 4 independent loads (MLP 4)
        const int row = o0 + osub + i * 4;
        const float w = __ldg(&wv[row]);
        const float4 x = __ldcs(&((const float4*)(W + (size_t)row * H2))[h4]);
        acc.x = fmaf(x.x, w, acc.x); acc.y = fmaf(x.y, w, acc.y);
        acc.z = fmaf(x.z, w, acc.z); acc.w = fmaf(x.w, w, acc.w);
    }
    red[threadIdx.x] = acc;
    __syncthreads();
    if (osub == 0) {                            // fixed-order fold 4 -> 1
        float4 r0 = red[hl],       r1 = red[hl + 64];
        float4 r2 = red[hl + 128], r3 = red[hl + 192];
        float4 s;
        s.x = (r0.x + r1.x) + (r2.x + r3.x);
        s.y = (r0.y + r1.y) + (r2.y + r3.y);
        s.z = (r0.z + r1.z) + (r2.z + r3.z);
        s.w = (r0.w + r1.w) + (r2.w + r3.w);
        ((float4*)g_vpart[blockIdx.y])[h4] = s;
    }
}

// K1b (PDL): fold NOC=64 partials into g_v, fixed order. grid 4 x 256.
__global__ void __launch_bounds__(256) k1b_fold(void) {
    cudaGridDependencySynchronize();
    const int h = blockIdx.x * 256 + threadIdx.x;
    float s = 0.f;
#pragma unroll
    for (int c = 0; c < NOC; c++) s += g_vpart[c][h];
    g_v[h] = s;
}

// K2 (flash, PDL): FULL cp.async 3-stage ring over the K-loop. Groups 0,1
// issued BEFORE the dependency sync (hides k1a/k1b); loads never occupy
// registers. grid 2048 x 256; 8 warps x 4 rows.
__global__ void __launch_bounds__(256) k2_energy(const float* __restrict__ outs,
                                                 float* __restrict__ out) {
    // Ring: 3 stages x [row(32) x lane(32)] float4 = 48 KB; conflict-free.
    __shared__ __align__(16) float4 sx[3 * 1024];
    __shared__ __align__(16) float sv[H2];
    __shared__ float se[32];
    __shared__ float smax[8];
    __shared__ float sm_b;

    const int warp = threadIdx.x >> 5, lane = threadIdx.x & 31;
    const int base_row = blockIdx.x * 32 + warp * 4;
    const float4* p0 = (const float4*)(outs + (size_t)(base_row + 0) * H2);
    const float4* p1 = (const float4*)(outs + (size_t)(base_row + 1) * H2);
    const float4* p2 = (const float4*)(outs + (size_t)(base_row + 2) * H2);
    const float4* p3 = (const float4*)(outs + (size_t)(base_row + 3) * H2);
    const int r0i = (warp * 4 + 0) * 32 + lane;
    const int r1i = (warp * 4 + 1) * 32 + lane;
    const int r2i = (warp * 4 + 2) * 32 + lane;
    const int r3i = (warp * 4 + 3) * 32 + lane;

    auto issue = [&](int it) {
        const int s = (it % 3) * 1024;
        const int j = it * 32 + lane;
        __pipeline_memcpy_async(&sx[s + r0i], &p0[j], 16);
        __pipeline_memcpy_async(&sx[s + r1i], &p1[j], 16);
        __pipeline_memcpy_async(&sx[s + r2i], &p2[j], 16);
        __pipeline_memcpy_async(&sx[s + r3i], &p3[j], 16);
        __pipeline_commit();
    };

    issue(0); issue(1);                         // in flight across the wait

    cudaGridDependencySynchronize();            // wait for g_v

    ((float4*)sv)[threadIdx.x] = ((const float4*)g_v)[threadIdx.x];
    __syncthreads();

    const float4* sv4 = (const float4*)sv;
    float a0 = 0.f, a1 = 0.f, a2 = 0.f, a3 = 0.f;

#pragma unroll
    for (int it = 0; it < 8; it++) {
        if (it + 2 < 8) issue(it + 2);          // ring slot (it+2)%3 is free
        __pipeline_wait_prior(it < 6 ? 2 : (7 - it));   // group `it` complete
        const int s = (it % 3) * 1024;
        float4 v  = sv4[it * 32 + lane];
        float4 x0 = sx[s + r0i], x1 = sx[s + r1i];
        float4 x2 = sx[s + r2i], x3 = sx[s + r3i];
        a0 = fmaf(x0.x, v.x, a0); a0 = fmaf(x0.y, v.y, a0);
        a0 = fmaf(x0.z, v.z, a0); a0 = fmaf(x0.w, v.w, a0);
        a1 = fmaf(x1.x, v.x, a1); a1 = fmaf(x1.y, v.y, a1);
        a1 = fmaf(x1.z, v.z, a1); a1 = fmaf(x1.w, v.w, a1);
        a2 = fmaf(x2.x, v.x, a2); a2 = fmaf(x2.y, v.y, a2);
        a2 = fmaf(x2.z, v.z, a2); a2 = fmaf(x2.w, v.w, a2);
        a3 = fmaf(x3.x, v.x, a3); a3 = fmaf(x3.y, v.y, a3);
        a3 = fmaf(x3.z, v.z, a3); a3 = fmaf(x3.w, v.w, a3);
    }
#pragma unroll
    for (int off = 16; off; off >>= 1) {
        a0 += __shfl_xor_sync(0xffffffffu, a0, off);
        a1 += __shfl_xor_sync(0xffffffffu, a1, off);
        a2 += __shfl_xor_sync(0xffffffffu, a2, off);
        a3 += __shfl_xor_sync(0xffffffffu, a3, off);
    }
    if (lane == 0) {
        const int lr = warp * 4;
        se[lr + 0] = a0; se[lr + 1] = a1; se[lr + 2] = a2; se[lr + 3] = a3;
        smax[warp] = fmaxf(fmaxf(a0, a1), fmaxf(a2, a3));
    }
    __syncthreads();
    if (threadIdx.x == 0) {
        float m = smax[0];
#pragma unroll
        for (int i = 1; i < 8; i++) m = fmaxf(m, smax[i]);
        sm_b = m;
    }
    __syncthreads();

    if (threadIdx.x < 32) {
        const float m = sm_b;
        float ex = __expf(se[threadIdx.x] - m);
        out[blockIdx.x * 32 + threadIdx.x] = ex;
        float s = ex;
#pragma unroll
        for (int off = 16; off; off >>= 1) s += __shfl_xor_sync(0xffffffffu, s, off);
        if (threadIdx.x == 0) { g_m[blockIdx.x] = m; g_s[blockIdx.x] = s; }
    }
}

// K3 (PDL): gmax + total via coalesced float4 stat loads, fixed trees
// (deterministic, redundant per block), then rescale. grid 32 x 512.
__global__ void __launch_bounds__(512) k3_norm(float* __restrict__ out) {
    cudaGridDependencySynchronize();            // wait for k2's out/g_m/g_s

    __shared__ float sm[512];
    const int t = threadIdx.x;

    const float4 m4 = ((const float4*)g_m)[t];
    float mm = fmaxf(fmaxf(m4.x, m4.y), fmaxf(m4.z, m4.w));
    sm[t] = mm;
    __syncthreads();
#pragma unroll
    for (int s = 256; s; s >>= 1) {
        if (t < s) sm[t] = fmaxf(sm[t], sm[t + s]);
        __syncthreads();
    }
    const float gmax = sm[0];
    __syncthreads();

    const float4 s4 = ((const float4*)g_s)[t];
    float ts = s4.x * __expf(m4.x - gmax) + s4.y * __expf(m4.y - gmax)
             + s4.z * __expf(m4.z - gmax) + s4.w * __expf(m4.w - gmax);
    sm[t] = ts;
    __syncthreads();
#pragma unroll
    for (int s = 256; s; s >>= 1) {
        if (t < s) sm[t] += sm[t + s];
        __syncthreads();
    }
    const float inv_total = 1.0f / sm[0];

    const int f4 = blockIdx.x * 512 + t;        // float4 index (32*512 = SEQN/4)
    const int b  = f4 >> 3;                     // 8 float4 per k2 block
    const float scale = __expf(g_m[b] - gmax) * inv_total;
    float4 r = ((const float4*)out)[f4];
    r.x *= scale; r.y *= scale; r.z *= scale; r.w *= scale;
    ((float4*)out)[f4] = r;
}

extern "C" void kernel_launch(void* const* d_in, const int* in_sizes, int n_in,
                              void* d_out, int out_size) {
    const float* outputs = (const float*)d_in[0];   // [SEQ, 2H]
    const float* W       = (const float*)d_in[1];   // [2H, 2H]
    // d_in[2] = b: constant shift, cancels in softmax -> unused
    const float* wv      = (const float*)d_in[3];   // [1, 2H]
    float* out = (float*)d_out;                     // [1,1,SEQ] float32

    k1a_v<<<dim3(4, NOC), 256>>>(W, wv);

    cudaLaunchAttribute pdl[1];
    pdl[0].id = cudaLaunchAttributeProgrammaticStreamSerialization;
    pdl[0].val.programmaticStreamSerializationAllowed = 1;

    cudaLaunchConfig_t cfg1b = {};
    cfg1b.gridDim = dim3(H2 / 256); cfg1b.blockDim = dim3(256);
    cfg1b.stream = 0; cfg1b.attrs = pdl; cfg1b.numAttrs = 1;
    cudaLaunchKernelEx(&cfg1b, k1b_fold);

    cudaLaunchConfig_t cfg2 = {};
    cfg2.gridDim = dim3(K2B); cfg2.blockDim = dim3(256);
    cfg2.stream = 0; cfg2.attrs = pdl; cfg2.numAttrs = 1;
    cudaLaunchKernelEx(&cfg2, k2_energy, outputs, out);

    cudaLaunchConfig_t cfg3 = {};
    cfg3.gridDim = dim3(32); cfg3.blockDim = dim3(512);
    cfg3.stream = 0; cfg3.attrs = pdl; cfg3.numAttrs = 1;
    cudaLaunchKernelEx(&cfg3, k3_norm, out);
}

// round 15
// speedup vs baseline: 1.0338x; 1.0338x over previous
#include <cuda_runtime.h>
#include <cuda_pipeline.h>

#define H2    1024
#define SEQN  65536
#define NOC   64               // o-chunks (16 rows each) for k1a
#define K2B   (SEQN / 32)      // 2048 k2 blocks, 32 rows each

// Scratch (allocation-free rule: device globals)
__device__ __align__(16) float g_vpart[NOC][H2];
__device__ __align__(16) float g_v[H2];
__device__ __align__(16) float g_m[K2B];   // per-block energy max
__device__ __align__(16) float g_s[K2B];   // per-block sum of exp(e - m_b)

// K1a: partial v over one 16-row o-chunk, in-block fold 4->1.
// grid (4 h-quarters, NOC) = 256 blocks x 256 thr (proven shape).
__global__ void __launch_bounds__(256) k1a_v(const float* __restrict__ W,
                                             const float* __restrict__ wv) {
    __shared__ __align__(16) float4 red[256];
    const int osub = threadIdx.x >> 6;          // 0..3
    const int hl   = threadIdx.x & 63;          // local float4 index
    const int h4   = blockIdx.x * 64 + hl;      // global float4 index over h
    const int o0   = blockIdx.y * 16;

    float4 acc = make_float4(0.f, 0.f, 0.f, 0.f);
#pragma unroll
    for (int i = 0; i < 4; i++) {               // 4 independent loads (MLP 4)
        const int row = o0 + osub + i * 4;
        const float w = __ldg(&wv[row]);
        const float4 x = __ldcs(&((const float4*)(W + (size_t)row * H2))[h4]);
        acc.x = fmaf(x.x, w, acc.x); acc.y = fmaf(x.y, w, acc.y);
        acc.z = fmaf(x.z, w, acc.z); acc.w = fmaf(x.w, w, acc.w);
    }
    red[threadIdx.x] = acc;
    __syncthreads();
    if (osub == 0) {                            // fixed-order fold 4 -> 1
        float4 r0 = red[hl],       r1 = red[hl + 64];
        float4 r2 = red[hl + 128], r3 = red[hl + 192];
        float4 s;
        s.x = (r0.x + r1.x) + (r2.x + r3.x);
        s.y = (r0.y + r1.y) + (r2.y + r3.y);
        s.z = (r0.z + r1.z) + (r2.z + r3.z);
        s.w = (r0.w + r1.w) + (r2.w + r3.w);
        ((float4*)g_vpart[blockIdx.y])[h4] = s;
    }
}

// K1b (PDL): fold NOC=64 partials into g_v, fixed order. grid 4 x 256.
__global__ void __launch_bounds__(256) k1b_fold(void) {
    cudaGridDependencySynchronize();
    const int h = blockIdx.x * 256 + threadIdx.x;
    float s = 0.f;
#pragma unroll
    for (int c = 0; c < NOC; c++) s += g_vpart[c][h];
    g_v[h] = s;
}

// K2 (flash, PDL): stages it=0..2 into smem via cp.async BEFORE the dependency
// sync (upfront only — no in-loop waits; round-13 proven mechanism), then
// it=3..7 as scoreboarded LDG. grid 2048 x 256; 8 warps x 4 rows.
__global__ void __launch_bounds__(256) k2_energy(const float* __restrict__ outs,
                                                 float* __restrict__ out) {
    // Staging: [it][row][lane] float4 = 48 KB; lane-contiguous, conflict-free.
    __shared__ __align__(16) float4 sx[3 * 1024];
    __shared__ __align__(16) float sv[H2];
    __shared__ float se[32];
    __shared__ float smax[8];
    __shared__ float sm_b;

    const int warp = threadIdx.x >> 5, lane = threadIdx.x & 31;
    const int base_row = blockIdx.x * 32 + warp * 4;
    const float4* p0 = (const float4*)(outs + (size_t)(base_row + 0) * H2);
    const float4* p1 = (const float4*)(outs + (size_t)(base_row + 1) * H2);
    const float4* p2 = (const float4*)(outs + (size_t)(base_row + 2) * H2);
    const float4* p3 = (const float4*)(outs + (size_t)(base_row + 3) * H2);
    const int r0i = (warp * 4 + 0) * 32 + lane;
    const int r1i = (warp * 4 + 1) * 32 + lane;
    const int r2i = (warp * 4 + 2) * 32 + lane;
    const int r3i = (warp * 4 + 3) * 32 + lane;

#pragma unroll
    for (int it = 0; it < 3; it++) {            // 3 commit groups upfront
        const int s = it * 1024;
        const int j = it * 32 + lane;
        __pipeline_memcpy_async(&sx[s + r0i], &p0[j], 16);
        __pipeline_memcpy_async(&sx[s + r1i], &p1[j], 16);
        __pipeline_memcpy_async(&sx[s + r2i], &p2[j], 16);
        __pipeline_memcpy_async(&sx[s + r3i], &p3[j], 16);
        __pipeline_commit();
    }

    cudaGridDependencySynchronize();            // wait for g_v

    ((float4*)sv)[threadIdx.x] = ((const float4*)g_v)[threadIdx.x];
    __syncthreads();

    const float4* sv4 = (const float4*)sv;
    float a0 = 0.f, a1 = 0.f, a2 = 0.f, a3 = 0.f;

#pragma unroll
    for (int it = 0; it < 3; it++) {            // staged iterations from smem
        __pipeline_wait_prior(2 - it);          // descending, mostly non-blocking
        const int s = it * 1024;
        float4 v  = sv4[it * 32 + lane];
        float4 x0 = sx[s + r0i], x1 = sx[s + r1i];
        float4 x2 = sx[s + r2i], x3 = sx[s + r3i];
        a0 = fmaf(x0.x, v.x, a0); a0 = fmaf(x0.y, v.y, a0);
        a0 = fmaf(x0.z, v.z, a0); a0 = fmaf(x0.w, v.w, a0);
        a1 = fmaf(x1.x, v.x, a1); a1 = fmaf(x1.y, v.y, a1);
        a1 = fmaf(x1.z, v.z, a1); a1 = fmaf(x1.w, v.w, a1);
        a2 = fmaf(x2.x, v.x, a2); a2 = fmaf(x2.y, v.y, a2);
        a2 = fmaf(x2.z, v.z, a2); a2 = fmaf(x2.w, v.w, a2);
        a3 = fmaf(x3.x, v.x, a3); a3 = fmaf(x3.y, v.y, a3);
        a3 = fmaf(x3.z, v.z, a3); a3 = fmaf(x3.w, v.w, a3);
    }
#pragma unroll
    for (int it = 3; it < 8; it++) {            // deep-MLP LDG tail
        const int j = it * 32 + lane;
        float4 v = sv4[j];
        float4 x0 = __ldcs(&p0[j]), x1 = __ldcs(&p1[j]);
        float4 x2 = __ldcs(&p2[j]), x3 = __ldcs(&p3[j]);
        a0 = fmaf(x0.x, v.x, a0); a0 = fmaf(x0.y, v.y, a0);
        a0 = fmaf(x0.z, v.z, a0); a0 = fmaf(x0.w, v.w, a0);
        a1 = fmaf(x1.x, v.x, a1); a1 = fmaf(x1.y, v.y, a1);
        a1 = fmaf(x1.z, v.z, a1); a1 = fmaf(x1.w, v.w, a1);
        a2 = fmaf(x2.x, v.x, a2); a2 = fmaf(x2.y, v.y, a2);
        a2 = fmaf(x2.z, v.z, a2); a2 = fmaf(x2.w, v.w, a2);
        a3 = fmaf(x3.x, v.x, a3); a3 = fmaf(x3.y, v.y, a3);
        a3 = fmaf(x3.z, v.z, a3); a3 = fmaf(x3.w, v.w, a3);
    }
#pragma unroll
    for (int off = 16; off; off >>= 1) {
        a0 += __shfl_xor_sync(0xffffffffu, a0, off);
        a1 += __shfl_xor_sync(0xffffffffu, a1, off);
        a2 += __shfl_xor_sync(0xffffffffu, a2, off);
        a3 += __shfl_xor_sync(0xffffffffu, a3, off);
    }
    if (lane == 0) {
        const int lr = warp * 4;
        se[lr + 0] = a0; se[lr + 1] = a1; se[lr + 2] = a2; se[lr + 3] = a3;
        smax[warp] = fmaxf(fmaxf(a0, a1), fmaxf(a2, a3));
    }
    __syncthreads();
    if (threadIdx.x == 0) {
        float m = smax[0];
#pragma unroll
        for (int i = 1; i < 8; i++) m = fmaxf(m, smax[i]);
        sm_b = m;
    }
    __syncthreads();

    if (threadIdx.x < 32) {
        const float m = sm_b;
        float ex = __expf(se[threadIdx.x] - m);
        out[blockIdx.x * 32 + threadIdx.x] = ex;
        float s = ex;
#pragma unroll
        for (int off = 16; off; off >>= 1) s += __shfl_xor_sync(0xffffffffu, s, off);
        if (threadIdx.x == 0) { g_m[blockIdx.x] = m; g_s[blockIdx.x] = s; }
    }
}

// K3 (PDL): gmax + total via coalesced float4 stat loads, fixed trees
// (deterministic, redundant per block), then rescale. grid 32 x 512.
__global__ void __launch_bounds__(512) k3_norm(float* __restrict__ out) {
    cudaGridDependencySynchronize();            // wait for k2's out/g_m/g_s

    __shared__ float sm[512];
    const int t = threadIdx.x;

    const float4 m4 = ((const float4*)g_m)[t];
    float mm = fmaxf(fmaxf(m4.x, m4.y), fmaxf(m4.z, m4.w));
    sm[t] = mm;
    __syncthreads();
#pragma unroll
    for (int s = 256; s; s >>= 1) {
        if (t < s) sm[t] = fmaxf(sm[t], sm[t + s]);
        __syncthreads();
    }
    const float gmax = sm[0];
    __syncthreads();

    const float4 s4 = ((const float4*)g_s)[t];
    float ts = s4.x * __expf(m4.x - gmax) + s4.y * __expf(m4.y - gmax)
             + s4.z * __expf(m4.z - gmax) + s4.w * __expf(m4.w - gmax);
    sm[t] = ts;
    __syncthreads();
#pragma unroll
    for (int s = 256; s; s >>= 1) {
        if (t < s) sm[t] += sm[t + s];
        __syncthreads();
    }
    const float inv_total = 1.0f / sm[0];

    const int f4 = blockIdx.x * 512 + t;        // float4 index (32*512 = SEQN/4)
    const int b  = f4 >> 3;                     // 8 float4 per k2 block
    const float scale = __expf(g_m[b] - gmax) * inv_total;
    float4 r = ((const float4*)out)[f4];
    r.x *= scale; r.y *= scale; r.z *= scale; r.w *= scale;
    ((float4*)out)[f4] = r;
}

extern "C" void kernel_launch(void* const* d_in, const int* in_sizes, int n_in,
                              void* d_out, int out_size) {
    const float* outputs = (const float*)d_in[0];   // [SEQ, 2H]
    const float* W       = (const float*)d_in[1];   // [2H, 2H]
    // d_in[2] = b: constant shift, cancels in softmax -> unused
    const float* wv      = (const float*)d_in[3];   // [1, 2H]
    float* out = (float*)d_out;                     // [1,1,SEQ] float32

    k1a_v<<<dim3(4, NOC), 256>>>(W, wv);

    cudaLaunchAttribute pdl[1];
    pdl[0].id = cudaLaunchAttributeProgrammaticStreamSerialization;
    pdl[0].val.programmaticStreamSerializationAllowed = 1;

    cudaLaunchConfig_t cfg1b = {};
    cfg1b.gridDim = dim3(H2 / 256); cfg1b.blockDim = dim3(256);
    cfg1b.stream = 0; cfg1b.attrs = pdl; cfg1b.numAttrs = 1;
    cudaLaunchKernelEx(&cfg1b, k1b_fold);

    cudaLaunchConfig_t cfg2 = {};
    cfg2.gridDim = dim3(K2B); cfg2.blockDim = dim3(256);
    cfg2.stream = 0; cfg2.attrs = pdl; cfg2.numAttrs = 1;
    cudaLaunchKernelEx(&cfg2, k2_energy, outputs, out);

    cudaLaunchConfig_t cfg3 = {};
    cfg3.gridDim = dim3(32); cfg3.blockDim = dim3(512);
    cfg3.stream = 0; cfg3.attrs = pdl; cfg3.numAttrs = 1;
    cudaLaunchKernelEx(&cfg3, k3_norm, out);
}

// round 16
// speedup vs baseline: 1.1692x; 1.1310x over previous
#include <cuda_runtime.h>
#include <cuda_pipeline.h>

#define H2    1024
#define SEQN  65536
#define NOC   64               // o-chunks (16 rows each) for k1a
#define K2B   (SEQN / 32)      // 2048 k2 blocks, 32 rows each

// Scratch (allocation-free rule: device globals)
__device__ __align__(16) float g_vpart[NOC][H2];
__device__ __align__(16) float g_v[H2];
__device__ __align__(16) float g_m[K2B];   // per-block energy max
__device__ __align__(16) float g_s[K2B];   // per-block sum of exp(e - m_b)

// K1a: partial v over one 16-row o-chunk, in-block fold 4->1.
// grid (4 h-quarters, NOC) = 256 blocks x 256 thr (proven shape).
__global__ void __launch_bounds__(256) k1a_v(const float* __restrict__ W,
                                             const float* __restrict__ wv) {
    __shared__ __align__(16) float4 red[256];
    const int osub = threadIdx.x >> 6;          // 0..3
    const int hl   = threadIdx.x & 63;          // local float4 index
    const int h4   = blockIdx.x * 64 + hl;      // global float4 index over h
    const int o0   = blockIdx.y * 16;

    float4 acc = make_float4(0.f, 0.f, 0.f, 0.f);
#pragma unroll
    for (int i = 0; i < 4; i++) {               // 4 independent loads (MLP 4)
        const int row = o0 + osub + i * 4;
        const float w = __ldg(&wv[row]);
        const float4 x = __ldcs(&((const float4*)(W + (size_t)row * H2))[h4]);
        acc.x = fmaf(x.x, w, acc.x); acc.y = fmaf(x.y, w, acc.y);
        acc.z = fmaf(x.z, w, acc.z); acc.w = fmaf(x.w, w, acc.w);
    }
    red[threadIdx.x] = acc;
    __syncthreads();
    if (osub == 0) {                            // fixed-order fold 4 -> 1
        float4 r0 = red[hl],       r1 = red[hl + 64];
        float4 r2 = red[hl + 128], r3 = red[hl + 192];
        float4 s;
        s.x = (r0.x + r1.x) + (r2.x + r3.x);
        s.y = (r0.y + r1.y) + (r2.y + r3.y);
        s.z = (r0.z + r1.z) + (r2.z + r3.z);
        s.w = (r0.w + r1.w) + (r2.w + r3.w);
        ((float4*)g_vpart[blockIdx.y])[h4] = s;
    }
}

// K1b (PDL): fold NOC=64 partials into g_v, fixed order. grid 4 x 256.
__global__ void __launch_bounds__(256) k1b_fold(void) {
    cudaGridDependencySynchronize();
    const int h = blockIdx.x * 256 + threadIdx.x;
    float s = 0.f;
#pragma unroll
    for (int c = 0; c < NOC; c++) s += g_vpart[c][h];
    g_v[h] = s;
}

// K2 (flash, PDL): stages it=0,1 into smem via cp.async BEFORE the dependency
// sync (zero register cost; ~32KB/block in flight hides k1a/k1b; 6 blocks/SM),
// then it=2..7 as deep-MLP LDG. grid 2048 x 256; 8 warps x 4 rows.
__global__ void __launch_bounds__(256) k2_energy(const float* __restrict__ outs,
                                                 float* __restrict__ out) {
    // Staging: [warp][row r][it][lane] float4, lane-contiguous -> conflict-free.
    __shared__ __align__(16) float4 sx[2048];   // 32 KB
    __shared__ __align__(16) float sv[H2];
    __shared__ float se[32];
    __shared__ float smax[8];
    __shared__ float sm_b;

    const int warp = threadIdx.x >> 5, lane = threadIdx.x & 31;
    const int base_row = blockIdx.x * 32 + warp * 4;
    const float4* p0 = (const float4*)(outs + (size_t)(base_row + 0) * H2);
    const float4* p1 = (const float4*)(outs + (size_t)(base_row + 1) * H2);
    const float4* p2 = (const float4*)(outs + (size_t)(base_row + 2) * H2);
    const float4* p3 = (const float4*)(outs + (size_t)(base_row + 3) * H2);

#pragma unroll
    for (int it = 0; it < 2; it++) {
        const int j = it * 32 + lane;
        __pipeline_memcpy_async(&sx[(((warp * 4 + 0) * 2) + it) * 32 + lane], &p0[j], 16);
        __pipeline_memcpy_async(&sx[(((warp * 4 + 1) * 2) + it) * 32 + lane], &p1[j], 16);
        __pipeline_memcpy_async(&sx[(((warp * 4 + 2) * 2) + it) * 32 + lane], &p2[j], 16);
        __pipeline_memcpy_async(&sx[(((warp * 4 + 3) * 2) + it) * 32 + lane], &p3[j], 16);
    }
    __pipeline_commit();

    cudaGridDependencySynchronize();            // wait for g_v

    ((float4*)sv)[threadIdx.x] = ((const float4*)g_v)[threadIdx.x];
    __syncthreads();

    const float4* sv4 = (const float4*)sv;
    float a0 = 0.f, a1 = 0.f, a2 = 0.f, a3 = 0.f;

    __pipeline_wait_prior(0);                   // own staged data ready
    {   // it = 0,1 from smem staging
#pragma unroll
        for (int it = 0; it < 2; it++) {
            float4 v  = sv4[it * 32 + lane];
            float4 x0 = sx[(((warp * 4 + 0) * 2) + it) * 32 + lane];
            float4 x1 = sx[(((warp * 4 + 1) * 2) + it) * 32 + lane];
            float4 x2 = sx[(((warp * 4 + 2) * 2) + it) * 32 + lane];
            float4 x3 = sx[(((warp * 4 + 3) * 2) + it) * 32 + lane];
            a0 = fmaf(x0.x, v.x, a0); a0 = fmaf(x0.y, v.y, a0);
            a0 = fmaf(x0.z, v.z, a0); a0 = fmaf(x0.w, v.w, a0);
            a1 = fmaf(x1.x, v.x, a1); a1 = fmaf(x1.y, v.y, a1);
            a1 = fmaf(x1.z, v.z, a1); a1 = fmaf(x1.w, v.w, a1);
            a2 = fmaf(x2.x, v.x, a2); a2 = fmaf(x2.y, v.y, a2);
            a2 = fmaf(x2.z, v.z, a2); a2 = fmaf(x2.w, v.w, a2);
            a3 = fmaf(x3.x, v.x, a3); a3 = fmaf(x3.y, v.y, a3);
            a3 = fmaf(x3.z, v.z, a3); a3 = fmaf(x3.w, v.w, a3);
        }
    }
#pragma unroll
    for (int it = 2; it < 8; it++) {            // it = 2..7 from global
        const int j = it * 32 + lane;
        float4 v = sv4[j];
        float4 x0 = __ldcs(&p0[j]), x1 = __ldcs(&p1[j]);
        float4 x2 = __ldcs(&p2[j]), x3 = __ldcs(&p3[j]);
        a0 = fmaf(x0.x, v.x, a0); a0 = fmaf(x0.y, v.y, a0);
        a0 = fmaf(x0.z, v.z, a0); a0 = fmaf(x0.w, v.w, a0);
        a1 = fmaf(x1.x, v.x, a1); a1 = fmaf(x1.y, v.y, a1);
        a1 = fmaf(x1.z, v.z, a1); a1 = fmaf(x1.w, v.w, a1);
        a2 = fmaf(x2.x, v.x, a2); a2 = fmaf(x2.y, v.y, a2);
        a2 = fmaf(x2.z, v.z, a2); a2 = fmaf(x2.w, v.w, a2);
        a3 = fmaf(x3.x, v.x, a3); a3 = fmaf(x3.y, v.y, a3);
        a3 = fmaf(x3.z, v.z, a3); a3 = fmaf(x3.w, v.w, a3);
    }
#pragma unroll
    for (int off = 16; off; off >>= 1) {
        a0 += __shfl_xor_sync(0xffffffffu, a0, off);
        a1 += __shfl_xor_sync(0xffffffffu, a1, off);
        a2 += __shfl_xor_sync(0xffffffffu, a2, off);
        a3 += __shfl_xor_sync(0xffffffffu, a3, off);
    }
    if (lane == 0) {
        const int lr = warp * 4;
        se[lr + 0] = a0; se[lr + 1] = a1; se[lr + 2] = a2; se[lr + 3] = a3;
        smax[warp] = fmaxf(fmaxf(a0, a1), fmaxf(a2, a3));
    }
    __syncthreads();
    if (threadIdx.x == 0) {
        float m = smax[0];
#pragma unroll
        for (int i = 1; i < 8; i++) m = fmaxf(m, smax[i]);
        sm_b = m;
    }
    __syncthreads();

    if (threadIdx.x < 32) {
        const float m = sm_b;
        float ex = __expf(se[threadIdx.x] - m);
        out[blockIdx.x * 32 + threadIdx.x] = ex;
        float s = ex;
#pragma unroll
        for (int off = 16; off; off >>= 1) s += __shfl_xor_sync(0xffffffffu, s, off);
        if (threadIdx.x == 0) { g_m[blockIdx.x] = m; g_s[blockIdx.x] = s; }
    }
}

// K3 (PDL): gmax + total via coalesced float4 stat loads, fixed trees
// (deterministic, redundant per block), then rescale. grid 32 x 512.
__global__ void __launch_bounds__(512) k3_norm(float* __restrict__ out) {
    cudaGridDependencySynchronize();            // wait for k2's out/g_m/g_s

    __shared__ float sm[512];
    const int t = threadIdx.x;

    const float4 m4 = ((const float4*)g_m)[t];
    float mm = fmaxf(fmaxf(m4.x, m4.y), fmaxf(m4.z, m4.w));
    sm[t] = mm;
    __syncthreads();
#pragma unroll
    for (int s = 256; s; s >>= 1) {
        if (t < s) sm[t] = fmaxf(sm[t], sm[t + s]);
        __syncthreads();
    }
    const float gmax = sm[0];
    __syncthreads();

    const float4 s4 = ((const float4*)g_s)[t];
    float ts = s4.x * __expf(m4.x - gmax) + s4.y * __expf(m4.y - gmax)
             + s4.z * __expf(m4.z - gmax) + s4.w * __expf(m4.w - gmax);
    sm[t] = ts;
    __syncthreads();
#pragma unroll
    for (int s = 256; s; s >>= 1) {
        if (t < s) sm[t] += sm[t + s];
        __syncthreads();
    }
    const float inv_total = 1.0f / sm[0];

    const int f4 = blockIdx.x * 512 + t;        // float4 index (32*512 = SEQN/4)
    const int b  = f4 >> 3;                     // 8 float4 per k2 block
    const float scale = __expf(g_m[b] - gmax) * inv_total;
    float4 r = ((const float4*)out)[f4];
    r.x *= scale; r.y *= scale; r.z *= scale; r.w *= scale;
    ((float4*)out)[f4] = r;
}

extern "C" void kernel_launch(void* const* d_in, const int* in_sizes, int n_in,
                              void* d_out, int out_size) {
    const float* outputs = (const float*)d_in[0];   // [SEQ, 2H]
    const float* W       = (const float*)d_in[1];   // [2H, 2H]
    // d_in[2] = b: constant shift, cancels in softmax -> unused
    const float* wv      = (const float*)d_in[3];   // [1, 2H]
    float* out = (float*)d_out;                     // [1,1,SEQ] float32

    k1a_v<<<dim3(4, NOC), 256>>>(W, wv);

    cudaLaunchAttribute pdl[1];
    pdl[0].id = cudaLaunchAttributeProgrammaticStreamSerialization;
    pdl[0].val.programmaticStreamSerializationAllowed = 1;

    cudaLaunchConfig_t cfg1b = {};
    cfg1b.gridDim = dim3(H2 / 256); cfg1b.blockDim = dim3(256);
    cfg1b.stream = 0; cfg1b.attrs = pdl; cfg1b.numAttrs = 1;
    cudaLaunchKernelEx(&cfg1b, k1b_fold);

    cudaLaunchConfig_t cfg2 = {};
    cfg2.gridDim = dim3(K2B); cfg2.blockDim = dim3(256);
    cfg2.stream = 0; cfg2.attrs = pdl; cfg2.numAttrs = 1;
    cudaLaunchKernelEx(&cfg2, k2_energy, outputs, out);

    cudaLaunchConfig_t cfg3 = {};
    cfg3.gridDim = dim3(32); cfg3.blockDim = dim3(512);
    cfg3.stream = 0; cfg3.attrs = pdl; cfg3.numAttrs = 1;
    cudaLaunchKernelEx(&cfg3, k3_norm, out);
}